// round 1
// baseline (speedup 1.0000x reference)
#include <cuda_runtime.h>
#include <cstdint>
#include <cfloat>
#include <math.h>

#define NNODES 50000
#define NEDGES 800000
#define FDIM   256
#define NH     4
#define CH     64
#define TOPK   10
#define NEG_SLOPE 0.2f

// ---------------- scratch (device globals; no allocations anywhere) ----------------
__device__ float g_xl   [(size_t)NNODES * FDIM];
__device__ float g_h1   [(size_t)NNODES * FDIM];
__device__ float g_h2   [(size_t)NNODES * CH];
__device__ float g_as   [NNODES * NH];
__device__ float g_ad   [NNODES * NH];
__device__ float g_alpha[(size_t)NEDGES * NH];
__device__ float g_w    [(size_t)NEDGES * NH];
__device__ float g_thr  [NNODES * NH];
__device__ int   g_thrid[NNODES * NH];
__device__ float g_m    [NNODES * NH];
__device__ float g_invd [NNODES * NH];
__device__ int   g_counts[NNODES];
__device__ int   g_rowptr[NNODES + 1];
__device__ int   g_cursor[NNODES];
__device__ int   g_src  [NEDGES];
__device__ int   g_dst  [NEDGES];
__device__ int   g_eid  [NEDGES];
__device__ int   g_csrsrc[NEDGES];
__device__ int   g_is64;

// ---------------- CSR build ----------------
__global__ void k_detect(const void* ei) {
    if (blockIdx.x == 0 && threadIdx.x == 0) {
        const long long* p = (const long long*)ei;
        int ok = 1;
        for (int i = 0; i < 16; i++) {
            long long v = p[i];
            if (v < 0 || v >= NNODES) ok = 0;
        }
        g_is64 = ok;
    }
}

__global__ void k_zero_counts(int n) {
    int i = blockIdx.x * blockDim.x + threadIdx.x;
    if (i < n) g_counts[i] = 0;
}

__global__ void k_prep_edges(const void* ei, int E) {
    int e = blockIdx.x * blockDim.x + threadIdx.x;
    if (e >= E) return;
    int s, d;
    if (g_is64) {
        const long long* p = (const long long*)ei;
        s = (int)p[e];
        d = (int)p[(size_t)E + e];
    } else {
        const int* p = (const int*)ei;
        s = p[e];
        d = p[E + e];
    }
    g_src[e] = s;
    g_dst[e] = d;
    atomicAdd(&g_counts[d], 1);
}

__global__ void k_scan(int n) {
    __shared__ int wsum[32];
    int tid = threadIdx.x, lane = tid & 31, wid = tid >> 5;
    if (tid == 0) g_rowptr[0] = 0;
    int carry = 0;
    for (int base = 0; base < n; base += 8192) {
        int v[8]; int s = 0;
        #pragma unroll
        for (int j = 0; j < 8; j++) {
            int i = base + tid * 8 + j;
            int t = (i < n) ? g_counts[i] : 0;
            v[j] = t; s += t;
        }
        int ws = s;
        #pragma unroll
        for (int off = 1; off < 32; off <<= 1) {
            int t = __shfl_up_sync(0xffffffffu, ws, off);
            if (lane >= off) ws += t;
        }
        if (lane == 31) wsum[wid] = ws;
        __syncthreads();
        if (wid == 0) {
            int xx = wsum[lane];
            #pragma unroll
            for (int off = 1; off < 32; off <<= 1) {
                int t = __shfl_up_sync(0xffffffffu, xx, off);
                if (lane >= off) xx += t;
            }
            wsum[lane] = xx;
        }
        __syncthreads();
        int prefix = carry + (wid > 0 ? wsum[wid - 1] : 0) + (ws - s);
        int run = prefix;
        #pragma unroll
        for (int j = 0; j < 8; j++) {
            int i = base + tid * 8 + j;
            run += v[j];
            if (i < n) g_rowptr[i + 1] = run;
        }
        int total = wsum[31];
        __syncthreads();
        carry += total;
    }
}

__global__ void k_cursor(int n) {
    int i = blockIdx.x * blockDim.x + threadIdx.x;
    if (i < n) g_cursor[i] = g_rowptr[i];
}

__global__ void k_scatter(int E) {
    int e = blockIdx.x * blockDim.x + threadIdx.x;
    if (e >= E) return;
    int d = g_dst[e];
    int p = atomicAdd(&g_cursor[d], 1);
    g_eid[p] = e;
}

__global__ void k_segsort(int n) {
    int node = blockIdx.x * blockDim.x + threadIdx.x;
    if (node >= n) return;
    int s = g_rowptr[node], e = g_rowptr[node + 1];
    for (int i = s + 1; i < e; i++) {
        int v = g_eid[i];
        int j = i - 1;
        while (j >= s && g_eid[j] > v) { g_eid[j + 1] = g_eid[j]; j--; }
        g_eid[j + 1] = v;
    }
}

__global__ void k_csrsrc(int E) {
    int i = blockIdx.x * blockDim.x + threadIdx.x;
    if (i < E) g_csrsrc[i] = g_src[g_eid[i]];
}

// ---------------- fp32 GEMM: C[m,n] = sum_k A[m,k]*W[n,k], K=Nc=256 ----------------
#define GFETCH(k0) { \
    int gm0 = bm + lrow, gm1 = bm + lrow + 64; \
    ra0 = (gm0 < M) ? *(const float4*)(A + (size_t)gm0 * 256 + (k0) + lcol) : f4z; \
    ra1 = (gm1 < M) ? *(const float4*)(A + (size_t)gm1 * 256 + (k0) + lcol) : f4z; \
    rb0 = *(const float4*)(W + (size_t)(bn + lrow) * 256 + (k0) + lcol); \
    rb1 = *(const float4*)(W + (size_t)(bn + lrow + 64) * 256 + (k0) + lcol); }

#define GSTORE(b) { \
    As[b][lcol+0][lrow] = ra0.x; As[b][lcol+1][lrow] = ra0.y; As[b][lcol+2][lrow] = ra0.z; As[b][lcol+3][lrow] = ra0.w; \
    As[b][lcol+0][lrow+64] = ra1.x; As[b][lcol+1][lrow+64] = ra1.y; As[b][lcol+2][lrow+64] = ra1.z; As[b][lcol+3][lrow+64] = ra1.w; \
    Bs[b][lcol+0][lrow] = rb0.x; Bs[b][lcol+1][lrow] = rb0.y; Bs[b][lcol+2][lrow] = rb0.z; Bs[b][lcol+3][lrow] = rb0.w; \
    Bs[b][lcol+0][lrow+64] = rb1.x; Bs[b][lcol+1][lrow+64] = rb1.y; Bs[b][lcol+2][lrow+64] = rb1.z; Bs[b][lcol+3][lrow+64] = rb1.w; }

__global__ void __launch_bounds__(256) k_gemm(const float* __restrict__ Aext,
                                              const float* __restrict__ W,
                                              int M, int layer) {
    const float* A = (layer == 0) ? Aext : g_h1;
    float* C = g_xl;
    __shared__ float As[2][16][128];
    __shared__ float Bs[2][16][128];
    int tid = threadIdx.x;
    int bm = blockIdx.y * 128, bn = blockIdx.x * 128;
    int tm = (tid >> 4) * 8, tn = (tid & 15) * 8;
    int lrow = tid >> 2, lcol = (tid & 3) * 4;
    const float4 f4z = make_float4(0.f, 0.f, 0.f, 0.f);
    float4 ra0, ra1, rb0, rb1;
    float acc[8][8];
    #pragma unroll
    for (int i = 0; i < 8; i++)
        #pragma unroll
        for (int j = 0; j < 8; j++) acc[i][j] = 0.f;

    GFETCH(0); GSTORE(0);
    __syncthreads();
    int buf = 0;
    for (int t = 0; t < 16; t++) {
        if (t < 15) GFETCH((t + 1) * 16);
        #pragma unroll
        for (int kk = 0; kk < 16; kk++) {
            float a[8], b[8];
            *(float4*)(a)     = *(const float4*)&As[buf][kk][tm];
            *(float4*)(a + 4) = *(const float4*)&As[buf][kk][tm + 4];
            *(float4*)(b)     = *(const float4*)&Bs[buf][kk][tn];
            *(float4*)(b + 4) = *(const float4*)&Bs[buf][kk][tn + 4];
            #pragma unroll
            for (int i = 0; i < 8; i++)
                #pragma unroll
                for (int j = 0; j < 8; j++) acc[i][j] += a[i] * b[j];
        }
        if (t < 15) GSTORE(buf ^ 1);
        __syncthreads();
        buf ^= 1;
    }
    #pragma unroll
    for (int i = 0; i < 8; i++) {
        int gm = bm + tm + i;
        if (gm < M) {
            *(float4*)(C + (size_t)gm * 256 + bn + tn)     = make_float4(acc[i][0], acc[i][1], acc[i][2], acc[i][3]);
            *(float4*)(C + (size_t)gm * 256 + bn + tn + 4) = make_float4(acc[i][4], acc[i][5], acc[i][6], acc[i][7]);
        }
    }
}

// ---------------- attention dots ----------------
__global__ void k_attdot(const float* __restrict__ atts, const float* __restrict__ attd, int n) {
    int warp = blockIdx.x * (blockDim.x >> 5) + (threadIdx.x >> 5);
    int lane = threadIdx.x & 31;
    if (warp >= n) return;
    const float* row = g_xl + (size_t)warp * 256 + lane * 8;
    float4 x0 = *(const float4*)(row);
    float4 x1 = *(const float4*)(row + 4);
    float4 s0 = *(const float4*)(atts + lane * 8);
    float4 s1 = *(const float4*)(atts + lane * 8 + 4);
    float4 d0 = *(const float4*)(attd + lane * 8);
    float4 d1 = *(const float4*)(attd + lane * 8 + 4);
    float ps = x0.x * s0.x + x0.y * s0.y + x0.z * s0.z + x0.w * s0.w
             + x1.x * s1.x + x1.y * s1.y + x1.z * s1.z + x1.w * s1.w;
    float pd = x0.x * d0.x + x0.y * d0.y + x0.z * d0.z + x0.w * d0.w
             + x1.x * d1.x + x1.y * d1.y + x1.z * d1.z + x1.w * d1.w;
    #pragma unroll
    for (int off = 4; off >= 1; off >>= 1) {
        ps += __shfl_xor_sync(0xffffffffu, ps, off);
        pd += __shfl_xor_sync(0xffffffffu, pd, off);
    }
    if ((lane & 7) == 0) {
        int h = lane >> 3;
        g_as[warp * 4 + h] = ps;
        g_ad[warp * 4 + h] = pd;
    }
}

// ---------------- per-edge scores ----------------
__device__ __forceinline__ float lrelu(float x) { return x >= 0.f ? x : NEG_SLOPE * x; }

__global__ void k_alpha(int E) {
    int e = blockIdx.x * blockDim.x + threadIdx.x;
    if (e >= E) return;
    int s = g_src[e], d = g_dst[e];
    float4 a = *(const float4*)(g_as + s * 4);
    float4 b = *(const float4*)(g_ad + d * 4);
    float4 r;
    r.x = lrelu(a.x + b.x);
    r.y = lrelu(a.y + b.y);
    r.z = lrelu(a.z + b.z);
    r.w = lrelu(a.w + b.w);
    *(float4*)(g_alpha + (size_t)e * 4) = r;
}

// ---------------- top-K selection + softmax stats ----------------
__global__ void k_select(int n) {
    int t = blockIdx.x * blockDim.x + threadIdx.x;
    if (t >= n * 4) return;
    int node = t >> 2, h = t & 3;
    int s = g_rowptr[node], e_end = g_rowptr[node + 1];
    float tv[TOPK]; int ti[TOPK];
    int cnt = 0;
    for (int i = s; i < e_end; i++) {
        int e = g_eid[i];
        float a = g_alpha[(size_t)e * 4 + h];
        if (cnt < TOPK) {
            tv[cnt] = a; ti[cnt] = e;
            int p = cnt; cnt++;
            while (p > 0 && (tv[p] > tv[p - 1] || (tv[p] == tv[p - 1] && ti[p] < ti[p - 1]))) {
                float fv = tv[p]; tv[p] = tv[p - 1]; tv[p - 1] = fv;
                int iv = ti[p]; ti[p] = ti[p - 1]; ti[p - 1] = iv;
                p--;
            }
        } else if (a > tv[TOPK - 1]) {
            tv[TOPK - 1] = a; ti[TOPK - 1] = e;
            int p = TOPK - 1;
            while (p > 0 && (tv[p] > tv[p - 1] || (tv[p] == tv[p - 1] && ti[p] < ti[p - 1]))) {
                float fv = tv[p]; tv[p] = tv[p - 1]; tv[p - 1] = fv;
                int iv = ti[p]; ti[p] = ti[p - 1]; ti[p - 1] = iv;
                p--;
            }
        }
    }
    float m = (cnt > 0) ? tv[0] : 0.f;
    float den = 0.f;
    for (int i = 0; i < cnt; i++) den += expf(tv[i] - m);
    float thv; int tiv;
    if (cnt == TOPK && (e_end - s) > TOPK) { thv = tv[TOPK - 1]; tiv = ti[TOPK - 1]; }
    else { thv = -FLT_MAX; tiv = 0x7fffffff; }
    g_thr[t] = thv;
    g_thrid[t] = tiv;
    g_m[t] = m;
    g_invd[t] = (cnt > 0) ? 1.f / den : 0.f;
}

// ---------------- softmax weights per CSR position ----------------
__global__ void k_weights(int E) {
    int i = blockIdx.x * blockDim.x + threadIdx.x;
    if (i >= E) return;
    int e = g_eid[i];
    int d = g_dst[e];
    float4 a  = *(const float4*)(g_alpha + (size_t)e * 4);
    float4 th = *(const float4*)(g_thr   + d * 4);
    int4   ti = *(const int4*)  (g_thrid + d * 4);
    float4 mm = *(const float4*)(g_m     + d * 4);
    float4 iv = *(const float4*)(g_invd  + d * 4);
    float4 w;
    w.x = ((a.x > th.x) || (a.x == th.x && e <= ti.x)) ? expf(a.x - mm.x) * iv.x : 0.f;
    w.y = ((a.y > th.y) || (a.y == th.y && e <= ti.y)) ? expf(a.y - mm.y) * iv.y : 0.f;
    w.z = ((a.z > th.z) || (a.z == th.z && e <= ti.z)) ? expf(a.z - mm.z) * iv.z : 0.f;
    w.w = ((a.w > th.w) || (a.w == th.w && e <= ti.w)) ? expf(a.w - mm.w) * iv.w : 0.f;
    *(float4*)(g_w + (size_t)i * 4) = w;
}

// ---------------- aggregation ----------------
template <int MODE>
__global__ void __launch_bounds__(64) k_agg(const float* __restrict__ bias, int n) {
    __shared__ float sh[256];
    int node = blockIdx.x;
    int tid = threadIdx.x;
    int head = tid >> 4;
    int s = g_rowptr[node], e_end = g_rowptr[node + 1];
    float a0 = 0.f, a1 = 0.f, a2 = 0.f, a3 = 0.f;
    for (int i = s; i < e_end; i++) {
        int src = g_csrsrc[i];
        float w = g_w[(size_t)i * 4 + head];
        float4 v = *(const float4*)(g_xl + (size_t)src * 256 + tid * 4);
        a0 += w * v.x; a1 += w * v.y; a2 += w * v.z; a3 += w * v.w;
    }
    if (MODE == 0) {
        float4 b = *(const float4*)(bias + tid * 4);
        *(float4*)(g_h1 + (size_t)node * 256 + tid * 4) =
            make_float4(a0 + b.x, a1 + b.y, a2 + b.z, a3 + b.w);
    } else {
        sh[tid * 4 + 0] = a0; sh[tid * 4 + 1] = a1; sh[tid * 4 + 2] = a2; sh[tid * 4 + 3] = a3;
        __syncthreads();
        int c = tid;
        float v = 0.25f * (sh[c] + sh[64 + c] + sh[128 + c] + sh[192 + c]) + bias[c];
        g_h2[(size_t)node * 64 + c] = v;
    }
}

// ---------------- fused MLP head ----------------
__global__ void __launch_bounds__(128) k_head(const float* __restrict__ W1, const float* __restrict__ b1,
                                              const float* __restrict__ W2, const float* __restrict__ b2,
                                              float* __restrict__ out, int n) {
    __shared__ float xsh[32][64];
    __shared__ float hsh[32][128];
    __shared__ float w2t[128 * 16];
    __shared__ float b2s[16];
    int tid = threadIdx.x;
    int r0 = blockIdx.x * 32;
    for (int i = tid; i < 128 * 16; i += 128) {
        int k = i >> 4, o = i & 15;
        w2t[i] = W2[o * 128 + k];
    }
    if (tid < 16) b2s[tid] = b2[tid];
    for (int i = tid; i < 32 * 16; i += 128) {
        int r = i >> 4, c4 = (i & 15) * 4;
        float4 v = (r0 + r < n) ? *(const float4*)(g_h2 + (size_t)(r0 + r) * 64 + c4)
                                : make_float4(0.f, 0.f, 0.f, 0.f);
        *(float4*)&xsh[r][c4] = v;
    }
    __syncthreads();
    float wreg[64];
    #pragma unroll
    for (int k4 = 0; k4 < 16; k4++) {
        float4 v = *(const float4*)(W1 + tid * 64 + k4 * 4);
        wreg[k4 * 4 + 0] = v.x; wreg[k4 * 4 + 1] = v.y; wreg[k4 * 4 + 2] = v.z; wreg[k4 * 4 + 3] = v.w;
    }
    float bias1 = b1[tid];
    for (int r = 0; r < 32; r++) {
        float sacc = bias1;
        #pragma unroll
        for (int k = 0; k < 64; k++) sacc += wreg[k] * xsh[r][k];
        hsh[r][tid] = fmaxf(sacc, 0.f);
    }
    __syncthreads();
    for (int t = tid; t < 512; t += 128) {
        int r = t >> 4, o = t & 15;
        float sacc = b2s[o];
        #pragma unroll
        for (int k = 0; k < 128; k++) sacc += hsh[r][k] * w2t[k * 16 + o];
        if (r0 + r < n) out[(size_t)(r0 + r) * 16 + o] = sacc;
    }
}

// ---------------- launch ----------------
extern "C" void kernel_launch(void* const* d_in, const int* in_sizes, int n_in,
                              void* d_out, int out_size) {
    (void)n_in; (void)out_size;
    const float* x   = (const float*)d_in[0];
    const float* W1  = (const float*)d_in[1];
    const float* as1 = (const float*)d_in[2];
    const float* ad1 = (const float*)d_in[3];
    const float* b1  = (const float*)d_in[4];
    const float* W2  = (const float*)d_in[5];
    const float* as2 = (const float*)d_in[6];
    const float* ad2 = (const float*)d_in[7];
    const float* b2  = (const float*)d_in[8];
    const float* Wl1 = (const float*)d_in[9];
    const float* bl1 = (const float*)d_in[10];
    const float* Wl2 = (const float*)d_in[11];
    const float* bl2 = (const float*)d_in[12];
    const void*  ei  = d_in[13];
    float* out = (float*)d_out;

    int Nn = in_sizes[0] / FDIM;
    int Ee = in_sizes[13] / 2;

    k_detect<<<1, 32>>>(ei);
    k_zero_counts<<<(Nn + 255) / 256, 256>>>(Nn);
    k_prep_edges<<<(Ee + 255) / 256, 256>>>(ei, Ee);
    k_scan<<<1, 1024>>>(Nn);
    k_cursor<<<(Nn + 255) / 256, 256>>>(Nn);
    k_scatter<<<(Ee + 255) / 256, 256>>>(Ee);
    k_segsort<<<(Nn + 127) / 128, 128>>>(Nn);
    k_csrsrc<<<(Ee + 255) / 256, 256>>>(Ee);

    dim3 gg(2, (Nn + 127) / 128);

    // layer 1
    k_gemm<<<gg, 256>>>(x, W1, Nn, 0);
    k_attdot<<<(Nn + 7) / 8, 256>>>(as1, ad1, Nn);
    k_alpha<<<(Ee + 255) / 256, 256>>>(Ee);
    k_select<<<(Nn * 4 + 127) / 128, 128>>>(Nn);
    k_weights<<<(Ee + 255) / 256, 256>>>(Ee);
    k_agg<0><<<Nn, 64>>>(b1, Nn);

    // layer 2
    k_gemm<<<gg, 256>>>(x, W2, Nn, 1);
    k_attdot<<<(Nn + 7) / 8, 256>>>(as2, ad2, Nn);
    k_alpha<<<(Ee + 255) / 256, 256>>>(Ee);
    k_select<<<(Nn * 4 + 127) / 128, 128>>>(Nn);
    k_weights<<<(Ee + 255) / 256, 256>>>(Ee);
    k_agg<1><<<Nn, 64>>>(b2, Nn);

    // head
    k_head<<<(Nn + 31) / 32, 128>>>(Wl1, bl1, Wl2, bl2, out, Nn);
}